// round 13
// baseline (speedup 1.0000x reference)
#include <cuda_runtime.h>
#include <cuda_fp16.h>
#include <cstdint>
#include <cstddef>

// Problem dims
#define M_DIM 8192
#define N_DIM 4096
#define K_DIM 4096

// Tiling: CTA tile 128x128, K-step 64 fp16 = 128B rows (sw128), 2 CTAs/SM.
#define M_TILES 64
#define N_TILES 32
#define K_TILES 64
#define STAGES 3
#define BLK_BYTES 16384               // one 128x64 fp16 block
#define STAGE_BYTES (2 * BLK_BYTES)   // A | B
#define OFF_SCAL (STAGES * STAGE_BYTES)
#define SMEM_BYTES (OFF_SCAL + 1024)  // 99328 B -> 2 CTAs fit in 228KB

// Packed, pre-swizzled global scratch (allocation-free: __device__ globals)
static __device__ __align__(1024) __half g_w [(size_t)N_DIM * K_DIM];
static __device__ __align__(1024) __half g_x [(size_t)M_DIM * K_DIM];

__device__ __forceinline__ uint32_t sw128(uint32_t off) {
    return off ^ ((off >> 3) & 0x70u);
}

__device__ __forceinline__ uint32_t smem_u32(const void* p) {
    uint32_t a;
    asm("{ .reg .u64 t; cvta.to.shared.u64 t, %1; cvt.u32.u64 %0, t; }" : "=r"(a) : "l"(p));
    return a;
}

// fp16 convert + pack: low 16 bits = element at LOWER k (little-endian order).
__device__ __forceinline__ uint32_t pack_half(float even_k, float odd_k) {
    __half h0 = __float2half_rn(even_k);
    __half h1 = __float2half_rn(odd_k);
    uint16_t u0 = *(const uint16_t*)&h0;
    uint16_t u1 = *(const uint16_t*)&h1;
    return (uint32_t)u0 | ((uint32_t)u1 << 16);
}

__device__ __forceinline__ void cp16(uint32_t dst, const void* src) {
    asm volatile("cp.async.cg.shared.global [%0], [%1], 16;" :: "r"(dst), "l"(src));
}

__device__ __forceinline__ void ldsm4(uint32_t* r, uint32_t addr) {
    asm volatile("ldmatrix.sync.aligned.m8n8.x4.shared.b16 {%0,%1,%2,%3}, [%4];"
        : "=r"(r[0]), "=r"(r[1]), "=r"(r[2]), "=r"(r[3]) : "r"(addr) : "memory");
}

__device__ __forceinline__ void mma16816(float* c, const uint32_t* a, uint32_t b0, uint32_t b1) {
    asm volatile("mma.sync.aligned.m16n8k16.row.col.f32.f16.f16.f32 "
        "{%0,%1,%2,%3}, {%4,%5,%6,%7}, {%8,%9}, {%0,%1,%2,%3};"
        : "+f"(c[0]), "+f"(c[1]), "+f"(c[2]), "+f"(c[3])
        : "r"(a[0]), "r"(a[1]), "r"(a[2]), "r"(a[3]), "r"(b0), "r"(b1));
}

// ---------------------------------------------------------------------------
// Merged prologue: blocks [0,4096) convert INT32 weight -> fp16 (exact),
// blocks [4096,20480) convert fp32 x -> fp16. Both tile-major + sw128
// pre-swizzled. W block id = k_tile*32 + n_blk ; A block id = m_blk*64 + k_tile.
// ---------------------------------------------------------------------------
__global__ __launch_bounds__(256)
void conv_all_kernel(const int* __restrict__ w, const float* __restrict__ x) {
    if (blockIdx.x < 4096) {
        int idx = blockIdx.x * blockDim.x + threadIdx.x;     // 0 .. 1048575
        int n  = idx >> 8;
        int kc = (idx & 255) << 4;                           // 16 values per thread
        const int4* src = (const int4*)(w + (size_t)n * K_DIM + kc);
        int4 v0 = src[0], v1 = src[1], v2 = src[2], v3 = src[3];
        int vals[16] = { v0.x, v0.y, v0.z, v0.w, v1.x, v1.y, v1.z, v1.w,
                         v2.x, v2.y, v2.z, v2.w, v3.x, v3.y, v3.z, v3.w };
        uint32_t o[8];
#pragma unroll
        for (int i = 0; i < 8; i++)
            o[i] = pack_half((float)vals[2*i], (float)vals[2*i+1]);
        int n_blk = n >> 7, r = n & 127, k_tile = kc >> 6, c = kc & 63;
        size_t blk = (size_t)(k_tile * 32 + n_blk) * BLK_BYTES;
        uint32_t off = (uint32_t)(r * 128 + c * 2);
        *(uint4*)((char*)g_w + blk + sw128(off))      = make_uint4(o[0], o[1], o[2], o[3]);
        *(uint4*)((char*)g_w + blk + sw128(off + 16)) = make_uint4(o[4], o[5], o[6], o[7]);
    } else {
        int idx = (blockIdx.x - 4096) * blockDim.x + threadIdx.x;  // 0 .. 4194303
        int m  = idx >> 9;
        int k8 = (idx & 511) << 3;                           // 8 floats per thread
        const float4* p = (const float4*)(x + (size_t)m * K_DIM + k8);
        float4 a = p[0], b = p[1];
        float f[8] = {a.x, a.y, a.z, a.w, b.x, b.y, b.z, b.w};
        uint32_t o[4];
#pragma unroll
        for (int i = 0; i < 4; i++)
            o[i] = pack_half(f[2*i], f[2*i+1]);
        int m_blk = m >> 7, r = m & 127, k_tile = k8 >> 6, c = k8 & 63;
        size_t base = (size_t)(m_blk * 64 + k_tile) * BLK_BYTES
                    + sw128((uint32_t)(r * 128 + c * 2));
        *(uint4*)((char*)g_x + base) = make_uint4(o[0], o[1], o[2], o[3]);
    }
}

// ---------------------------------------------------------------------------
// Main GEMM: 3-stage cp.async + fp16 HMMA. CTA 128x128, 256 threads,
// warp grid 4(m)x2(n), warp tile 32x64, **2 CTAs per SM** (launch_bounds 256,2):
// two independent barrier domains per SM so one CTA's HMMAs cover the other's
// ldsm/sync phases (R11 ncu showed single-CTA lockstep: tensor=60%, nothing
// saturated). 256 threads also restores register headroom for ptxas hoisting.
// ldmatrix addressing: row = lane&15, half = (lane>>4)*16, xor = (lane&7)<<4.
// B pair for n8 block j of an n16 ldsm quad: {q[j], q[j+2]}.
// Pipeline: stage s holds kt with kt%3==s; at tile t: wait_group 1 (oldest of
// the 2 pending groups = kt t), sync (frees stage (t-1)%3), refill kt t+2.
// ---------------------------------------------------------------------------
__global__ __launch_bounds__(256, 2)
void gemm_kernel(float* __restrict__ out, const float* __restrict__ scaler) {
    extern __shared__ __align__(1024) char smem[];
    uint32_t sbase = smem_u32(smem);
    int tid = threadIdx.x, lane = tid & 31, wid = tid >> 5;
    int n_tile = blockIdx.x & 31, m_tile = blockIdx.x >> 5;   // n fastest: W stays L2-hot
    int warp_m = wid & 3, warp_n = wid >> 2;

    if (tid < 128)
        ((float*)(smem + OFF_SCAL))[tid] = scaler[n_tile * 128 + tid];

    const char* gA = (const char*)g_x + (size_t)(m_tile * 64) * BLK_BYTES;
    const char* gB = (const char*)g_w + (size_t)n_tile * BLK_BYTES;

    int r16 = lane & 15;
    uint32_t bytesel = (uint32_t)((lane >> 4) * 16);
    uint32_t rxor    = (uint32_t)((lane & 7) << 4);
    uint32_t a_off[2], b_off[4];
#pragma unroll
    for (int mt = 0; mt < 2; mt++)
        a_off[mt] = (uint32_t)((warp_m * 32 + mt * 16 + r16) * 128);
#pragma unroll
    for (int p = 0; p < 4; p++)
        b_off[p] = (uint32_t)((warp_n * 64 + p * 16 + r16) * 128);

    float c[2][8][4];
#pragma unroll
    for (int mt = 0; mt < 2; mt++)
#pragma unroll
        for (int nt = 0; nt < 8; nt++)
#pragma unroll
            for (int j = 0; j < 4; j++) c[mt][nt][j] = 0.f;

    auto load_stage = [&](int s, int kt) {
        uint32_t dst = sbase + (uint32_t)s * STAGE_BYTES;
        const char* sA = gA + (size_t)kt * BLK_BYTES;
        const char* sB = gB + (size_t)kt * (32 * BLK_BYTES);
#pragma unroll
        for (int r = 0; r < 4; r++) {
            uint32_t off = (uint32_t)((r * 256 + tid) * 16);
            cp16(dst + off,             sA + off);
            cp16(dst + BLK_BYTES + off, sB + off);
        }
        asm volatile("cp.async.commit_group;" ::: "memory");
    };

    load_stage(0, 0);
    load_stage(1, 1);            // pending = {kt0, kt1}

    for (int t = 0; t < K_TILES; t++) {
        // Entry invariant: pending = {kt t, kt t+1} (or just {kt t} at the tail).
        if (t < K_TILES - 1)
            asm volatile("cp.async.wait_group 1;" ::: "memory");  // kt t landed
        else
            asm volatile("cp.async.wait_group 0;" ::: "memory");
        __syncthreads();                 // all warps done reading stage (t-1)%3

        // Refill the stage freed by the sync: kt t+2 -> stage (t+2)%3 == (t-1)%3.
        if (t + 2 < K_TILES) load_stage((t + 2) % STAGES, t + 2);

        uint32_t st = sbase + (uint32_t)(t % STAGES) * STAGE_BYTES;
        uint32_t aBs = st, bBs = st + BLK_BYTES;
#pragma unroll
        for (int k16 = 0; k16 < 4; k16++) {
            uint32_t low = ((uint32_t)(k16 * 32) | bytesel) ^ rxor;
            uint32_t q[4][4];
#pragma unroll
            for (int p = 0; p < 4; p++) ldsm4(q[p], bBs + b_off[p] + low);
            uint32_t ah[2][4];
#pragma unroll
            for (int mt = 0; mt < 2; mt++) ldsm4(ah[mt], aBs + a_off[mt] + low);
#pragma unroll
            for (int mt = 0; mt < 2; mt++)
#pragma unroll
                for (int nt = 0; nt < 8; nt++)
                    mma16816(c[mt][nt], ah[mt],
                             q[nt >> 1][nt & 1], q[nt >> 1][(nt & 1) + 2]);
        }
    }

    // Epilogue: scale by per-output-channel weight_scaler, write fp32
    const float* scl = (const float*)(smem + OFF_SCAL);
    int lr = lane >> 2, lc = (lane & 3) * 2;
#pragma unroll
    for (int mt = 0; mt < 2; mt++) {
        int row = m_tile * 128 + warp_m * 32 + mt * 16 + lr;
#pragma unroll
        for (int nt = 0; nt < 8; nt++) {
            int cloc = warp_n * 64 + nt * 8 + lc;
            float s0 = scl[cloc], s1 = scl[cloc + 1];
            size_t g0 = (size_t)row * N_DIM + (size_t)(n_tile * 128 + cloc);
            float2 v0 = make_float2(c[mt][nt][0] * s0, c[mt][nt][1] * s1);
            float2 v1 = make_float2(c[mt][nt][2] * s0, c[mt][nt][3] * s1);
            *(float2*)(out + g0)                     = v0;
            *(float2*)(out + g0 + 8 * (size_t)N_DIM) = v1;
        }
    }
}

// ---------------------------------------------------------------------------
extern "C" void kernel_launch(void* const* d_in, const int* in_sizes, int n_in,
                              void* d_out, int out_size) {
    // Size-based input resolution: x 33554432, weight 16777216, scaler 4096
    const float* x  = 0;
    const int*   w  = 0;
    const float* ws = 0;
    for (int i = 0; i < n_in; i++) {
        if (in_sizes[i] == 33554432)      x  = (const float*)d_in[i];
        else if (in_sizes[i] == 16777216) w  = (const int*)d_in[i];
        else if (in_sizes[i] == 4096)     ws = (const float*)d_in[i];
    }
    float* o = (float*)d_out;

    cudaFuncSetAttribute(gemm_kernel, cudaFuncAttributeMaxDynamicSharedMemorySize, SMEM_BYTES);

    conv_all_kernel<<<20480, 256>>>(w, x);
    gemm_kernel<<<M_TILES * N_TILES, 256, SMEM_BYTES>>>(o, ws);
}

// round 14
// speedup vs baseline: 1.0020x; 1.0020x over previous
#include <cuda_runtime.h>
#include <cuda_fp16.h>
#include <cstdint>
#include <cstddef>

// Problem dims
#define M_DIM 8192
#define N_DIM 4096
#define K_DIM 4096

// Tiling: CTA tile 128x128, K-step 64 fp16 = 128B rows (sw128), 2 CTAs/SM.
#define M_TILES 64
#define N_TILES 32
#define K_TILES 64
#define STAGES 3
#define BLK_BYTES 16384               // one 128x64 fp16 block
#define STAGE_BYTES (2 * BLK_BYTES)   // A | B
#define OFF_SCAL (STAGES * STAGE_BYTES)
#define SMEM_BYTES (OFF_SCAL + 1024)  // 99328 B -> 2 CTAs fit in 228KB

// Packed, pre-swizzled global scratch (allocation-free: __device__ globals)
static __device__ __align__(1024) __half g_w [(size_t)N_DIM * K_DIM];
static __device__ __align__(1024) __half g_x [(size_t)M_DIM * K_DIM];

__device__ __forceinline__ uint32_t sw128(uint32_t off) {
    return off ^ ((off >> 3) & 0x70u);
}

__device__ __forceinline__ uint32_t smem_u32(const void* p) {
    uint32_t a;
    asm("{ .reg .u64 t; cvta.to.shared.u64 t, %1; cvt.u32.u64 %0, t; }" : "=r"(a) : "l"(p));
    return a;
}

// fp16 convert + pack: low 16 bits = element at LOWER k (little-endian order).
__device__ __forceinline__ uint32_t pack_half(float even_k, float odd_k) {
    __half h0 = __float2half_rn(even_k);
    __half h1 = __float2half_rn(odd_k);
    uint16_t u0 = *(const uint16_t*)&h0;
    uint16_t u1 = *(const uint16_t*)&h1;
    return (uint32_t)u0 | ((uint32_t)u1 << 16);
}

__device__ __forceinline__ void cp16(uint32_t dst, const void* src) {
    asm volatile("cp.async.cg.shared.global [%0], [%1], 16;" :: "r"(dst), "l"(src));
}

__device__ __forceinline__ void ldsm4(uint32_t* r, uint32_t addr) {
    asm volatile("ldmatrix.sync.aligned.m8n8.x4.shared.b16 {%0,%1,%2,%3}, [%4];"
        : "=r"(r[0]), "=r"(r[1]), "=r"(r[2]), "=r"(r[3]) : "r"(addr) : "memory");
}

__device__ __forceinline__ void mma16816(float* c, const uint32_t* a, uint32_t b0, uint32_t b1) {
    asm volatile("mma.sync.aligned.m16n8k16.row.col.f32.f16.f16.f32 "
        "{%0,%1,%2,%3}, {%4,%5,%6,%7}, {%8,%9}, {%0,%1,%2,%3};"
        : "+f"(c[0]), "+f"(c[1]), "+f"(c[2]), "+f"(c[3])
        : "r"(a[0]), "r"(a[1]), "r"(a[2]), "r"(a[3]), "r"(b0), "r"(b1));
}

// ---------------------------------------------------------------------------
// Merged prologue: blocks [0,4096) convert INT32 weight -> fp16 (exact),
// blocks [4096,20480) convert fp32 x -> fp16. Both tile-major + sw128
// pre-swizzled. W block id = k_tile*32 + n_blk ; A block id = m_blk*64 + k_tile.
// ---------------------------------------------------------------------------
__global__ __launch_bounds__(256)
void conv_all_kernel(const int* __restrict__ w, const float* __restrict__ x) {
    if (blockIdx.x < 4096) {
        int idx = blockIdx.x * blockDim.x + threadIdx.x;     // 0 .. 1048575
        int n  = idx >> 8;
        int kc = (idx & 255) << 4;                           // 16 values per thread
        const int4* src = (const int4*)(w + (size_t)n * K_DIM + kc);
        int4 v0 = src[0], v1 = src[1], v2 = src[2], v3 = src[3];
        int vals[16] = { v0.x, v0.y, v0.z, v0.w, v1.x, v1.y, v1.z, v1.w,
                         v2.x, v2.y, v2.z, v2.w, v3.x, v3.y, v3.z, v3.w };
        uint32_t o[8];
#pragma unroll
        for (int i = 0; i < 8; i++)
            o[i] = pack_half((float)vals[2*i], (float)vals[2*i+1]);
        int n_blk = n >> 7, r = n & 127, k_tile = kc >> 6, c = kc & 63;
        size_t blk = (size_t)(k_tile * 32 + n_blk) * BLK_BYTES;
        uint32_t off = (uint32_t)(r * 128 + c * 2);
        *(uint4*)((char*)g_w + blk + sw128(off))      = make_uint4(o[0], o[1], o[2], o[3]);
        *(uint4*)((char*)g_w + blk + sw128(off + 16)) = make_uint4(o[4], o[5], o[6], o[7]);
    } else {
        int idx = (blockIdx.x - 4096) * blockDim.x + threadIdx.x;  // 0 .. 4194303
        int m  = idx >> 9;
        int k8 = (idx & 511) << 3;                           // 8 floats per thread
        const float4* p = (const float4*)(x + (size_t)m * K_DIM + k8);
        float4 a = p[0], b = p[1];
        float f[8] = {a.x, a.y, a.z, a.w, b.x, b.y, b.z, b.w};
        uint32_t o[4];
#pragma unroll
        for (int i = 0; i < 4; i++)
            o[i] = pack_half(f[2*i], f[2*i+1]);
        int m_blk = m >> 7, r = m & 127, k_tile = k8 >> 6, c = k8 & 63;
        size_t base = (size_t)(m_blk * 64 + k_tile) * BLK_BYTES
                    + sw128((uint32_t)(r * 128 + c * 2));
        *(uint4*)((char*)g_x + base) = make_uint4(o[0], o[1], o[2], o[3]);
    }
}

// ---------------------------------------------------------------------------
// Main GEMM: 3-stage cp.async + fp16 HMMA. CTA 128x128, 256 threads,
// warp grid 4(m)x2(n), warp tile 32x64, **2 CTAs per SM** (launch_bounds 256,2):
// two independent barrier domains per SM so one CTA's HMMAs cover the other's
// ldsm/sync phases (R11 ncu showed single-CTA lockstep: tensor=60%, nothing
// saturated). 256 threads also restores register headroom for ptxas hoisting.
// ldmatrix addressing: row = lane&15, half = (lane>>4)*16, xor = (lane&7)<<4.
// B pair for n8 block j of an n16 ldsm quad: {q[j], q[j+2]}.
// Pipeline: stage s holds kt with kt%3==s; at tile t: wait_group 1 (oldest of
// the 2 pending groups = kt t), sync (frees stage (t-1)%3), refill kt t+2.
// ---------------------------------------------------------------------------
__global__ __launch_bounds__(256, 2)
void gemm_kernel(float* __restrict__ out, const float* __restrict__ scaler) {
    extern __shared__ __align__(1024) char smem[];
    uint32_t sbase = smem_u32(smem);
    int tid = threadIdx.x, lane = tid & 31, wid = tid >> 5;
    int n_tile = blockIdx.x & 31, m_tile = blockIdx.x >> 5;   // n fastest: W stays L2-hot
    int warp_m = wid & 3, warp_n = wid >> 2;

    if (tid < 128)
        ((float*)(smem + OFF_SCAL))[tid] = scaler[n_tile * 128 + tid];

    const char* gA = (const char*)g_x + (size_t)(m_tile * 64) * BLK_BYTES;
    const char* gB = (const char*)g_w + (size_t)n_tile * BLK_BYTES;

    int r16 = lane & 15;
    uint32_t bytesel = (uint32_t)((lane >> 4) * 16);
    uint32_t rxor    = (uint32_t)((lane & 7) << 4);
    uint32_t a_off[2], b_off[4];
#pragma unroll
    for (int mt = 0; mt < 2; mt++)
        a_off[mt] = (uint32_t)((warp_m * 32 + mt * 16 + r16) * 128);
#pragma unroll
    for (int p = 0; p < 4; p++)
        b_off[p] = (uint32_t)((warp_n * 64 + p * 16 + r16) * 128);

    float c[2][8][4];
#pragma unroll
    for (int mt = 0; mt < 2; mt++)
#pragma unroll
        for (int nt = 0; nt < 8; nt++)
#pragma unroll
            for (int j = 0; j < 4; j++) c[mt][nt][j] = 0.f;

    auto load_stage = [&](int s, int kt) {
        uint32_t dst = sbase + (uint32_t)s * STAGE_BYTES;
        const char* sA = gA + (size_t)kt * BLK_BYTES;
        const char* sB = gB + (size_t)kt * (32 * BLK_BYTES);
#pragma unroll
        for (int r = 0; r < 4; r++) {
            uint32_t off = (uint32_t)((r * 256 + tid) * 16);
            cp16(dst + off,             sA + off);
            cp16(dst + BLK_BYTES + off, sB + off);
        }
        asm volatile("cp.async.commit_group;" ::: "memory");
    };

    load_stage(0, 0);
    load_stage(1, 1);            // pending = {kt0, kt1}

    for (int t = 0; t < K_TILES; t++) {
        // Entry invariant: pending = {kt t, kt t+1} (or just {kt t} at the tail).
        if (t < K_TILES - 1)
            asm volatile("cp.async.wait_group 1;" ::: "memory");  // kt t landed
        else
            asm volatile("cp.async.wait_group 0;" ::: "memory");
        __syncthreads();                 // all warps done reading stage (t-1)%3

        // Refill the stage freed by the sync: kt t+2 -> stage (t+2)%3 == (t-1)%3.
        if (t + 2 < K_TILES) load_stage((t + 2) % STAGES, t + 2);

        uint32_t st = sbase + (uint32_t)(t % STAGES) * STAGE_BYTES;
        uint32_t aBs = st, bBs = st + BLK_BYTES;
#pragma unroll
        for (int k16 = 0; k16 < 4; k16++) {
            uint32_t low = ((uint32_t)(k16 * 32) | bytesel) ^ rxor;
            uint32_t q[4][4];
#pragma unroll
            for (int p = 0; p < 4; p++) ldsm4(q[p], bBs + b_off[p] + low);
            uint32_t ah[2][4];
#pragma unroll
            for (int mt = 0; mt < 2; mt++) ldsm4(ah[mt], aBs + a_off[mt] + low);
#pragma unroll
            for (int mt = 0; mt < 2; mt++)
#pragma unroll
                for (int nt = 0; nt < 8; nt++)
                    mma16816(c[mt][nt], ah[mt],
                             q[nt >> 1][nt & 1], q[nt >> 1][(nt & 1) + 2]);
        }
    }

    // Epilogue: scale by per-output-channel weight_scaler, write fp32
    const float* scl = (const float*)(smem + OFF_SCAL);
    int lr = lane >> 2, lc = (lane & 3) * 2;
#pragma unroll
    for (int mt = 0; mt < 2; mt++) {
        int row = m_tile * 128 + warp_m * 32 + mt * 16 + lr;
#pragma unroll
        for (int nt = 0; nt < 8; nt++) {
            int cloc = warp_n * 64 + nt * 8 + lc;
            float s0 = scl[cloc], s1 = scl[cloc + 1];
            size_t g0 = (size_t)row * N_DIM + (size_t)(n_tile * 128 + cloc);
            float2 v0 = make_float2(c[mt][nt][0] * s0, c[mt][nt][1] * s1);
            float2 v1 = make_float2(c[mt][nt][2] * s0, c[mt][nt][3] * s1);
            *(float2*)(out + g0)                     = v0;
            *(float2*)(out + g0 + 8 * (size_t)N_DIM) = v1;
        }
    }
}

// ---------------------------------------------------------------------------
extern "C" void kernel_launch(void* const* d_in, const int* in_sizes, int n_in,
                              void* d_out, int out_size) {
    // Size-based input resolution: x 33554432, weight 16777216, scaler 4096
    const float* x  = 0;
    const int*   w  = 0;
    const float* ws = 0;
    for (int i = 0; i < n_in; i++) {
        if (in_sizes[i] == 33554432)      x  = (const float*)d_in[i];
        else if (in_sizes[i] == 16777216) w  = (const int*)d_in[i];
        else if (in_sizes[i] == 4096)     ws = (const float*)d_in[i];
    }
    float* o = (float*)d_out;

    cudaFuncSetAttribute(gemm_kernel, cudaFuncAttributeMaxDynamicSharedMemorySize, SMEM_BYTES);

    conv_all_kernel<<<20480, 256>>>(w, x);
    gemm_kernel<<<M_TILES * N_TILES, 256, SMEM_BYTES>>>(o, ws);
}